// round 14
// baseline (speedup 1.0000x reference)
#include <cuda_runtime.h>
#include <cuda_bf16.h>
#include <cstdint>

// ---------------------------------------------------------------------------
// Problem constants
// ---------------------------------------------------------------------------
#define NMAX 50000
#define EMAX 400000
#define INCH 256
#define MBK   391                     // ceil(50000/128)
#define RSQRT_C 0.08838834764831845f  // 1/sqrt(128)

// ---------------------------------------------------------------------------
// Scratch (static __device__; allocation APIs are forbidden)
// ---------------------------------------------------------------------------
__device__ float g_nf[(size_t)NMAX * 1536];     // [q|k|v|(skip->out)|qw0|qw1]
__device__ float g_agg[(size_t)NMAX * 512];     // normalized edge_attr aggregate
__device__ float g_wbig[256 * 1536];            // fp32 combined weight [k][n]
__device__ float g_bbig[1536];
__device__ int   g_deg[NMAX];
__device__ int   g_rowptr[NMAX + 1];
__device__ int   g_cursor[NMAX];
__device__ int   g_esorted[EMAX];

// Fragment-ordered bf16 operands (uint = packed bf16x2).
__align__(16) __device__ unsigned int g_a1hi[(size_t)MBK * 16 * 1024];
__align__(16) __device__ unsigned int g_a1lo[(size_t)MBK * 16 * 1024];
__align__(16) __device__ unsigned int g_aghi[(size_t)MBK * 32 * 1024];  // 2 heads x 16kt
__align__(16) __device__ unsigned int g_aglo[(size_t)MBK * 32 * 1024];
__align__(16) __device__ unsigned int g_b1hi[12 * 16 * 1024];
__align__(16) __device__ unsigned int g_b1lo[12 * 16 * 1024];
__align__(16) __device__ unsigned int g_b2hi[2 * 16 * 1024];
__align__(16) __device__ unsigned int g_b2lo[2 * 16 * 1024];

// ---------------------------------------------------------------------------
// Helpers
// ---------------------------------------------------------------------------
__device__ __forceinline__ float cos_small(float u) {
    float s = u * u;
    float p = fmaf(s, 2.48015873e-5f, -1.38888889e-3f);
    p = fmaf(p, s, 4.16666667e-2f);
    p = fmaf(p, s, -0.5f);
    return fmaf(p, s, 1.0f);
}
__device__ __forceinline__ int clampi(int v, int hi) {
    return v < 0 ? 0 : (v >= hi ? hi - 1 : v);
}
__device__ __forceinline__ unsigned int pack2(float v0, float v1) {
    unsigned short s0 = __bfloat16_as_ushort(__float2bfloat16(v0));
    unsigned short s1 = __bfloat16_as_ushort(__float2bfloat16(v1));
    return (unsigned int)s0 | ((unsigned int)s1 << 16);
}
__device__ __forceinline__ float bf16f(float v) {
    return __bfloat162float(__float2bfloat16(v));
}

__global__ void zero_int_kernel(int* __restrict__ p, int n) {
    int i = blockIdx.x * blockDim.x + threadIdx.x;
    if (i < n) p[i] = 0;
}

// ---------------------------------------------------------------------------
// CSR build: histogram -> single-block scan -> scatter
// ---------------------------------------------------------------------------
__global__ void hist_kernel(const int* __restrict__ ei, int E, int N) {
    int e = blockIdx.x * blockDim.x + threadIdx.x;
    if (e >= E) return;
    atomicAdd(&g_deg[clampi(ei[E + e], N)], 1);
}

__global__ void scan_kernel(int N) {
    __shared__ int part[1024];
    int tid = threadIdx.x;
    int chunk = (N + 1023) >> 10;
    int start = tid * chunk;
    int end = min(start + chunk, N);
    int s = 0;
    for (int i = start; i < end; i++) s += g_deg[i];
    part[tid] = s;
    __syncthreads();
    for (int off = 1; off < 1024; off <<= 1) {
        int v = (tid >= off) ? part[tid - off] : 0;
        __syncthreads();
        part[tid] += v;
        __syncthreads();
    }
    int base = (tid == 0) ? 0 : part[tid - 1];
    for (int i = start; i < end; i++) {
        g_rowptr[i] = base;
        g_cursor[i] = base;
        base += g_deg[i];
    }
    if (tid == 1023) g_rowptr[N] = part[1023];
}

__global__ void scatter_kernel(const int* __restrict__ ei, int E, int N) {
    int e = blockIdx.x * blockDim.x + threadIdx.x;
    if (e >= E) return;
    int dst = clampi(ei[E + e], N);
    int pos = atomicAdd(&g_cursor[dst], 1);
    g_esorted[pos] = e;
}

// ---------------------------------------------------------------------------
// Weight prep: Wbig[256 x 1536] = [Wq|Wk|Wv|Wskip|Wqe0|Wqe1], bias similarly.
// ---------------------------------------------------------------------------
__global__ void pack_wbig_kernel(const float* __restrict__ Wq, const float* __restrict__ bq,
                                 const float* __restrict__ Wk, const float* __restrict__ bk,
                                 const float* __restrict__ Wv, const float* __restrict__ bv,
                                 const float* __restrict__ Wskip, const float* __restrict__ bskip,
                                 const float* __restrict__ We) {
    int gid = blockIdx.x * blockDim.x + threadIdx.x;
    if (gid < 256 * 1536) {
        int i = gid / 1536, j = gid % 1536;
        float v;
        if      (j < 256)  v = Wq[i * 256 + j];
        else if (j < 512)  v = Wk[i * 256 + (j - 256)];
        else if (j < 768)  v = Wv[i * 256 + (j - 512)];
        else if (j < 1024) v = Wskip[i * 256 + (j - 768)];
        else {
            int h = (j - 1024) >> 8, d = (j - 1024) & 255;
            float s = 0.f;
            for (int c = 0; c < 128; c++)
                s = fmaf(Wq[i * 256 + h * 128 + c], We[d * 256 + h * 128 + c], s);
            v = s;
        }
        g_wbig[gid] = v;
    }
    if (gid < 1536) {
        int j = gid;
        float v;
        if      (j < 256)  v = bq[j];
        else if (j < 512)  v = bk[j - 256];
        else if (j < 768)  v = bv[j - 512];
        else if (j < 1024) v = bskip[j - 768];
        else {
            int h = (j - 1024) >> 8, d = (j - 1024) & 255;
            float s = 0.f;
            for (int c = 0; c < 128; c++)
                s = fmaf(bq[h * 128 + c], We[d * 256 + h * 128 + c], s);
            v = s;
        }
        g_bbig[j] = v;
    }
}

// ---------------------------------------------------------------------------
// A fragment conversion (mma.m16n8k16 A-layout, hi/lo split), row stride lda
// ---------------------------------------------------------------------------
__global__ void conv_afrag_kernel(const float* __restrict__ A, int lda,
                                  unsigned int* __restrict__ hi,
                                  unsigned int* __restrict__ lo,
                                  int M, int K) {
    int nKT = K >> 4;
    int total = MBK * nKT * 1024;
    int gid = blockIdx.x * blockDim.x + threadIdx.x;
    if (gid >= total) return;
    int u = gid & 1023;
    int mbkt = gid >> 10;
    int mb = mbkt / nKT, kt = mbkt - mb * nKT;
    int mt = u >> 7;
    int lane = (u >> 2) & 31;
    int reg = u & 3;
    int row = mb * 128 + mt * 16 + (lane >> 2) + ((reg & 1) ? 8 : 0);
    int kc  = kt * 16 + ((lane & 3) * 2) + ((reg & 2) ? 8 : 0);
    float v0 = 0.f, v1 = 0.f;
    if (row < M) {
        v0 = A[(size_t)row * lda + kc];
        v1 = A[(size_t)row * lda + kc + 1];
    }
    float h0 = bf16f(v0), h1 = bf16f(v1);
    hi[gid] = pack2(v0, v1);
    lo[gid] = pack2(v0 - h0, v1 - h1);
}

// ---------------------------------------------------------------------------
// B fragment conversion (mma.m16n8k16 B-layout, hi/lo split)
// ---------------------------------------------------------------------------
__global__ void conv_bfrag_kernel(const float* __restrict__ B, int ldb,
                                  unsigned int* __restrict__ hi,
                                  unsigned int* __restrict__ lo,
                                  int K, int nNB) {
    int nKT = K >> 4;
    int total = nNB * nKT * 1024;
    int gid = blockIdx.x * blockDim.x + threadIdx.x;
    if (gid >= total) return;
    int reg = gid & 1;
    int lane = (gid >> 1) & 31;
    int nt = (gid >> 6) & 15;
    int nbkt = gid >> 10;
    int nb = nbkt / nKT, kt = nbkt - nb * nKT;
    int n = nb * 128 + nt * 8 + (lane >> 2);
    int k = kt * 16 + (lane & 3) * 2 + (reg ? 8 : 0);
    float v0 = B[(size_t)k * ldb + n];
    float v1 = B[(size_t)(k + 1) * ldb + n];
    float h0 = bf16f(v0), h1 = bf16f(v1);
    hi[gid] = pack2(v0, v1);
    lo[gid] = pack2(v0 - h0, v1 - h1);
}

// ---------------------------------------------------------------------------
// Tensor-core GEMM, smem-resident A, internal nb loop.
// 512 threads = 16 warps (4 wy x 4 wx), warp tile 32 x 32.
// A (hi+lo fragment-ordered, nKT*8KB) loaded to smem ONCE, reused for all nb.
// SKIP768: columns [768,1024) are redirected to Cskip (ldc 256, col-768).
// ---------------------------------------------------------------------------
#define MMA_BF16(c, a, b)                                                       \
    asm volatile("mma.sync.aligned.m16n8k16.row.col.f32.bf16.bf16.f32 "         \
        "{%0,%1,%2,%3}, {%4,%5,%6,%7}, {%8,%9}, {%0,%1,%2,%3};"                 \
        : "+f"((c)[0]), "+f"((c)[1]), "+f"((c)[2]), "+f"((c)[3])                \
        : "r"((a).x), "r"((a).y), "r"((a).z), "r"((a).w), "r"((b).x), "r"((b).y))

template <bool ACCUM, bool HASBIAS, bool SKIP768>
__global__ void __launch_bounds__(512)
mma_gemm_s(const uint4* __restrict__ Ahi, const uint4* __restrict__ Alo,
           const uint2* __restrict__ Bhi, const uint2* __restrict__ Blo,
           float* __restrict__ C, float* __restrict__ Cskip,
           const float* __restrict__ bias,
           int M, int ldc, int nKT, int nNB) {
    extern __shared__ uint4 smA[];   // [hi: nKT*256][lo: nKT*256] uint4
    const int mb = blockIdx.x;
    const int tid = threadIdx.x, lane = tid & 31, wid = tid >> 5;
    const int wy = wid >> 2, wx = wid & 3;
    const int totA = nKT * 256;      // uint4 per half

    {
        const uint4* gh = Ahi + (size_t)mb * totA;
        const uint4* gl = Alo + (size_t)mb * totA;
        for (int i = tid; i < totA; i += 512) {
            smA[i]        = gh[i];
            smA[totA + i] = gl[i];
        }
    }
    __syncthreads();

    for (int nb = 0; nb < nNB; nb++) {
        float acc[2][4][4];
#pragma unroll
        for (int i = 0; i < 2; i++)
#pragma unroll
            for (int j = 0; j < 4; j++)
#pragma unroll
                for (int r = 0; r < 4; r++) acc[i][j][r] = 0.f;

        for (int kt = 0; kt < nKT; kt++) {
            uint4 ah[2], al[2];
#pragma unroll
            for (int i = 0; i < 2; i++) {
                int idx = kt * 256 + (wy * 2 + i) * 32 + lane;
                ah[i] = smA[idx];
                al[i] = smA[totA + idx];
            }
            uint2 bh[4], bl[4];
#pragma unroll
            for (int j = 0; j < 4; j++) {
                size_t base = ((size_t)(nb * nKT + kt) * 16 + wx * 4 + j) * 32 + lane;
                bh[j] = Bhi[base];
                bl[j] = Blo[base];
            }
#pragma unroll
            for (int i = 0; i < 2; i++)
#pragma unroll
                for (int j = 0; j < 4; j++) {
                    MMA_BF16(acc[i][j], ah[i], bh[j]);
                    MMA_BF16(acc[i][j], ah[i], bl[j]);
                    MMA_BF16(acc[i][j], al[i], bh[j]);
                }
        }

#pragma unroll
        for (int i = 0; i < 2; i++) {
#pragma unroll
            for (int j = 0; j < 4; j++) {
                int row0 = mb * 128 + (wy * 2 + i) * 16 + (lane >> 2);
                int col  = nb * 128 + wx * 32 + j * 8 + (lane & 3) * 2;
                float b0 = 0.f, b1 = 0.f;
                if (HASBIAS) { b0 = bias[col]; b1 = bias[col + 1]; }
                bool toskip = SKIP768 && (col >= 768) && (col < 1024);
#pragma unroll
                for (int half = 0; half < 2; half++) {
                    int row = row0 + half * 8;
                    if (row >= M) continue;
                    float* p = toskip ? &Cskip[(size_t)row * 256 + (col - 768)]
                                      : &C[(size_t)row * ldc + col];
                    float2 v = make_float2(acc[i][j][2 * half + 0] + b0,
                                           acc[i][j][2 * half + 1] + b1);
                    if (ACCUM) { float2 o = *reinterpret_cast<float2*>(p); v.x += o.x; v.y += o.y; }
                    *reinterpret_cast<float2*>(p) = v;
                }
            }
        }
    }
}

// ---------------------------------------------------------------------------
// Fused warp-per-node attention with index prefetch (no atomics).
// ---------------------------------------------------------------------------
__global__ void node_fused_kernel(const int* __restrict__ ei,
                                  const float* __restrict__ last_update,
                                  const float* __restrict__ t,
                                  const float* __restrict__ msg,
                                  const float* __restrict__ Wt,
                                  const float* __restrict__ bt,
                                  float* __restrict__ out,
                                  int E, int N) {
    int n = (blockIdx.x * blockDim.x + threadIdx.x) >> 5;
    if (n >= N) return;
    int lane = threadIdx.x & 31;

    const float* nf = &g_nf[(size_t)n * 1536];
    float q[8], qw0[8], qw1[8];
#pragma unroll
    for (int i = 0; i < 8; i++) {
        q[i]   = nf[lane + 32 * i];
        qw0[i] = nf[1024 + lane + 32 * i];
        qw1[i] = nf[1280 + lane + 32 * i];
    }
    float wtr[4], btr[4];
#pragma unroll
    for (int i = 0; i < 4; i++) { wtr[i] = Wt[lane + 32 * i]; btr[i] = bt[lane + 32 * i]; }

    float agg0[8], agg1[8], vac[8];
#pragma unroll
    for (int i = 0; i < 8; i++) { agg0[i] = 0.f; agg1[i] = 0.f; vac[i] = 0.f; }
    float asum0 = 0.f, asum1 = 0.f;

    int beg = g_rowptr[n], end = g_rowptr[n + 1];

    // Prefetched index chain: esorted -> ei -> last_update (serial latency
    // overlapped with previous iteration's row loads).
    int e_n = 0, src_n = 0;
    float rel_n = 0.f;
    if (beg < end) {
        e_n = g_esorted[beg];
        src_n = clampi(ei[e_n], N);
        rel_n = last_update[src_n] - t[e_n];
    }

    for (int i = beg; i < end; i++) {
        int e = e_n, src = src_n;
        float rel_t = rel_n;
        if (i + 1 < end) {
            e_n = g_esorted[i + 1];
            src_n = clampi(ei[e_n], N);
            rel_n = last_update[src_n] - t[e_n];
        }

        const float* krow = &g_nf[(size_t)src * 1536 + 256];
        const float* vrow = &g_nf[(size_t)src * 1536 + 512];
        const float* mrow = &msg[(size_t)e * 128];

        float ea[8], vv[8];
        float s0 = 0.f, s1 = 0.f;
#pragma unroll
        for (int ii = 0; ii < 4; ii++) {
            int d = lane + 32 * ii;
            ea[ii] = cos_small(fmaf(rel_t, wtr[ii], btr[ii]));
            vv[ii] = vrow[d];
            s0 = fmaf(q[ii], krow[d], s0);
            s0 = fmaf(qw0[ii], ea[ii], s0);
            s1 = fmaf(qw1[ii], ea[ii], s1);
        }
#pragma unroll
        for (int ii = 4; ii < 8; ii++) {
            int d = lane + 32 * ii;
            ea[ii] = mrow[d - 128];
            vv[ii] = vrow[d];
            s1 = fmaf(q[ii], krow[d], s1);
            s0 = fmaf(qw0[ii], ea[ii], s0);
            s1 = fmaf(qw1[ii], ea[ii], s1);
        }
#pragma unroll
        for (int off = 16; off; off >>= 1) {
            s0 += __shfl_xor_sync(0xffffffffu, s0, off);
            s1 += __shfl_xor_sync(0xffffffffu, s1, off);
        }
        float a0 = __expf(s0 * RSQRT_C);
        float a1 = __expf(s1 * RSQRT_C);
        asum0 += a0;
        asum1 += a1;
#pragma unroll
        for (int ii = 0; ii < 8; ii++) {
            agg0[ii] = fmaf(a0, ea[ii], agg0[ii]);
            agg1[ii] = fmaf(a1, ea[ii], agg1[ii]);
        }
#pragma unroll
        for (int ii = 0; ii < 4; ii++) vac[ii] = fmaf(a0, vv[ii], vac[ii]);
#pragma unroll
        for (int ii = 4; ii < 8; ii++) vac[ii] = fmaf(a1, vv[ii], vac[ii]);
    }

    float inv0 = 1.f / (asum0 + 1e-16f);
    float inv1 = 1.f / (asum1 + 1e-16f);

    float* aggrow = &g_agg[(size_t)n * 512];
#pragma unroll
    for (int ii = 0; ii < 8; ii++) {
        aggrow[lane + 32 * ii]       = agg0[ii] * inv0;
        aggrow[256 + lane + 32 * ii] = agg1[ii] * inv1;
    }
    float* orow = &out[(size_t)n * 256];
#pragma unroll
    for (int ii = 0; ii < 4; ii++) {
        int idx = lane + 32 * ii;
        orow[idx]       += vac[ii] * inv0;
        orow[idx + 128] += vac[ii + 4] * inv1;
    }
}

// ---------------------------------------------------------------------------
// Host launcher
// ---------------------------------------------------------------------------
extern "C" void kernel_launch(void* const* d_in, const int* in_sizes, int n_in,
                              void* d_out, int out_size) {
    const float* x     = (const float*)d_in[0];
    const float* lastu = (const float*)d_in[1];
    const float* t     = (const float*)d_in[2];
    const float* msg   = (const float*)d_in[3];
    const int*   ei    = (const int*)d_in[4];   // int32 (JAX x64 disabled)
    const float* Wt    = (const float*)d_in[5];
    const float* bt    = (const float*)d_in[6];
    const float* Wq    = (const float*)d_in[7];
    const float* bq    = (const float*)d_in[8];
    const float* Wk    = (const float*)d_in[9];
    const float* bk    = (const float*)d_in[10];
    const float* Wv    = (const float*)d_in[11];
    const float* bv    = (const float*)d_in[12];
    const float* We    = (const float*)d_in[13];
    const float* Wskip = (const float*)d_in[14];
    const float* bskip = (const float*)d_in[15];
    float* out = (float*)d_out;

    const int N = in_sizes[0] / INCH;   // 50000
    const int E = in_sizes[2];          // 400000

    float *pNF, *pAGG, *pWBIG, *pBBIG;
    int *pDEG;
    unsigned int *pA1HI, *pA1LO, *pAGHI, *pAGLO, *pB1HI, *pB1LO, *pB2HI, *pB2LO;
    cudaGetSymbolAddress((void**)&pNF,   g_nf);
    cudaGetSymbolAddress((void**)&pAGG,  g_agg);
    cudaGetSymbolAddress((void**)&pWBIG, g_wbig);
    cudaGetSymbolAddress((void**)&pBBIG, g_bbig);
    cudaGetSymbolAddress((void**)&pDEG,  g_deg);
    cudaGetSymbolAddress((void**)&pA1HI, g_a1hi);
    cudaGetSymbolAddress((void**)&pA1LO, g_a1lo);
    cudaGetSymbolAddress((void**)&pAGHI, g_aghi);
    cudaGetSymbolAddress((void**)&pAGLO, g_aglo);
    cudaGetSymbolAddress((void**)&pB1HI, g_b1hi);
    cudaGetSymbolAddress((void**)&pB1LO, g_b1lo);
    cudaGetSymbolAddress((void**)&pB2HI, g_b2hi);
    cudaGetSymbolAddress((void**)&pB2LO, g_b2lo);

    // Dynamic smem: nKT=16 -> 2 * 16 * 256 * 16B = 128 KB (both GEMMs)
    const int SMEM_A = 2 * 16 * 256 * 16;
    cudaFuncSetAttribute((const void*)mma_gemm_s<false, true, true>,
                         cudaFuncAttributeMaxDynamicSharedMemorySize, SMEM_A);
    cudaFuncSetAttribute((const void*)mma_gemm_s<true, false, false>,
                         cudaFuncAttributeMaxDynamicSharedMemorySize, SMEM_A);

    // 0) CSR build
    zero_int_kernel<<<(N + 255) / 256, 256>>>(pDEG, N);
    hist_kernel<<<(E + 255) / 256, 256>>>(ei, E, N);
    scan_kernel<<<1, 1024>>>(N);
    scatter_kernel<<<(E + 255) / 256, 256>>>(ei, E, N);

    // 1) weight prep -> fragment conversion
    pack_wbig_kernel<<<(256 * 1536 + 255) / 256, 256>>>(Wq, bq, Wk, bk, Wv, bv, Wskip, bskip, We);
    conv_bfrag_kernel<<<(12 * 16 * 1024 + 255) / 256, 256>>>(pWBIG, 1536, pB1HI, pB1LO, 256, 12);
    for (int h = 0; h < 2; h++)
        conv_bfrag_kernel<<<(16 * 1024 + 255) / 256, 256>>>(
            We + h * 128, 256, pB2HI + h * 16 * 1024, pB2LO + h * 16 * 1024, 256, 1);

    // 2) x -> A fragments; GEMM1: g_nf = x @ Wbig + bbig (skip cols -> out)
    conv_afrag_kernel<<<(MBK * 16 * 1024 + 255) / 256, 256>>>(x, 256, pA1HI, pA1LO, N, 256);
    mma_gemm_s<false, true, true><<<MBK, 512, SMEM_A>>>(
        (const uint4*)pA1HI, (const uint4*)pA1LO,
        (const uint2*)pB1HI, (const uint2*)pB1LO, pNF, out, pBBIG, N, 1536, 16, 12);

    // 3) fused attention pass (writes g_agg, accumulates v-part into out)
    node_fused_kernel<<<(N * 32 + 255) / 256, 256>>>(ei, lastu, t, msg, Wt, bt, out, E, N);

    // 4) per-head agg -> A fragments; GEMM2: out[:, h*128:] += agg_h @ We_h
    for (int h = 0; h < 2; h++) {
        conv_afrag_kernel<<<(MBK * 16 * 1024 + 255) / 256, 256>>>(
            pAGG + h * 256, 512,
            pAGHI + (size_t)h * MBK * 16 * 1024, pAGLO + (size_t)h * MBK * 16 * 1024, N, 256);
        mma_gemm_s<true, false, false><<<MBK, 512, SMEM_A>>>(
            (const uint4*)(pAGHI + (size_t)h * MBK * 16 * 1024),
            (const uint4*)(pAGLO + (size_t)h * MBK * 16 * 1024),
            (const uint2*)(pB2HI + h * 16 * 1024), (const uint2*)(pB2LO + h * 16 * 1024),
            out + h * 128, nullptr, nullptr, N, 256, 16, 1);
    }
}

// round 15
// speedup vs baseline: 1.5038x; 1.5038x over previous
#include <cuda_runtime.h>
#include <cuda_fp16.h>
#include <cstdint>

// ---------------------------------------------------------------------------
// Problem constants
// ---------------------------------------------------------------------------
#define NMAX 50000
#define EMAX 400000
#define INCH 256
#define MBK   391                     // ceil(50000/128)
#define RSQRT_C 0.08838834764831845f  // 1/sqrt(128)

// ---------------------------------------------------------------------------
// Scratch (static __device__; allocation APIs are forbidden)
// ---------------------------------------------------------------------------
__device__ float g_nf[(size_t)NMAX * 1536];     // [q|k|v|(skip->out)|qw0|qw1]
__device__ float g_agg[(size_t)NMAX * 512];     // normalized edge_attr aggregate
__device__ float g_wbig[256 * 1536];            // fp32 combined weight [k][n]
__device__ float g_bbig[1536];
__device__ int   g_deg[NMAX];
__device__ int   g_rowptr[NMAX + 1];
__device__ int   g_cursor[NMAX];
__device__ int   g_esorted[EMAX];

// Fragment-ordered fp16 operands (uint = packed half2).
__align__(16) __device__ unsigned int g_a1[(size_t)MBK * 16 * 1024];
__align__(16) __device__ unsigned int g_ag[(size_t)MBK * 32 * 1024];   // 2 heads x 16kt
__align__(16) __device__ unsigned int g_b1[12 * 16 * 1024];
__align__(16) __device__ unsigned int g_b2[2 * 16 * 1024];

// ---------------------------------------------------------------------------
// Helpers
// ---------------------------------------------------------------------------
__device__ __forceinline__ float cos_small(float u) {
    float s = u * u;
    float p = fmaf(s, 2.48015873e-5f, -1.38888889e-3f);
    p = fmaf(p, s, 4.16666667e-2f);
    p = fmaf(p, s, -0.5f);
    return fmaf(p, s, 1.0f);
}
__device__ __forceinline__ int clampi(int v, int hi) {
    return v < 0 ? 0 : (v >= hi ? hi - 1 : v);
}
__device__ __forceinline__ unsigned int packh2(float v0, float v1) {
    __half2 h = __floats2half2_rn(v0, v1);
    return *reinterpret_cast<unsigned int*>(&h);
}

__global__ void zero_int_kernel(int* __restrict__ p, int n) {
    int i = blockIdx.x * blockDim.x + threadIdx.x;
    if (i < n) p[i] = 0;
}

// ---------------------------------------------------------------------------
// CSR build: histogram -> single-block scan -> scatter
// ---------------------------------------------------------------------------
__global__ void hist_kernel(const int* __restrict__ ei, int E, int N) {
    int e = blockIdx.x * blockDim.x + threadIdx.x;
    if (e >= E) return;
    atomicAdd(&g_deg[clampi(ei[E + e], N)], 1);
}

__global__ void scan_kernel(int N) {
    __shared__ int part[1024];
    int tid = threadIdx.x;
    int chunk = (N + 1023) >> 10;
    int start = tid * chunk;
    int end = min(start + chunk, N);
    int s = 0;
    for (int i = start; i < end; i++) s += g_deg[i];
    part[tid] = s;
    __syncthreads();
    for (int off = 1; off < 1024; off <<= 1) {
        int v = (tid >= off) ? part[tid - off] : 0;
        __syncthreads();
        part[tid] += v;
        __syncthreads();
    }
    int base = (tid == 0) ? 0 : part[tid - 1];
    for (int i = start; i < end; i++) {
        g_rowptr[i] = base;
        g_cursor[i] = base;
        base += g_deg[i];
    }
    if (tid == 1023) g_rowptr[N] = part[1023];
}

__global__ void scatter_kernel(const int* __restrict__ ei, int E, int N) {
    int e = blockIdx.x * blockDim.x + threadIdx.x;
    if (e >= E) return;
    int dst = clampi(ei[E + e], N);
    int pos = atomicAdd(&g_cursor[dst], 1);
    g_esorted[pos] = e;
}

// ---------------------------------------------------------------------------
// Weight prep: Wbig[256 x 1536] = [Wq|Wk|Wv|Wskip|Wqe0|Wqe1], bias similarly.
// ---------------------------------------------------------------------------
__global__ void pack_wbig_kernel(const float* __restrict__ Wq, const float* __restrict__ bq,
                                 const float* __restrict__ Wk, const float* __restrict__ bk,
                                 const float* __restrict__ Wv, const float* __restrict__ bv,
                                 const float* __restrict__ Wskip, const float* __restrict__ bskip,
                                 const float* __restrict__ We) {
    int gid = blockIdx.x * blockDim.x + threadIdx.x;
    if (gid < 256 * 1536) {
        int i = gid / 1536, j = gid % 1536;
        float v;
        if      (j < 256)  v = Wq[i * 256 + j];
        else if (j < 512)  v = Wk[i * 256 + (j - 256)];
        else if (j < 768)  v = Wv[i * 256 + (j - 512)];
        else if (j < 1024) v = Wskip[i * 256 + (j - 768)];
        else {
            int h = (j - 1024) >> 8, d = (j - 1024) & 255;
            float s = 0.f;
            for (int c = 0; c < 128; c++)
                s = fmaf(Wq[i * 256 + h * 128 + c], We[d * 256 + h * 128 + c], s);
            v = s;
        }
        g_wbig[gid] = v;
    }
    if (gid < 1536) {
        int j = gid;
        float v;
        if      (j < 256)  v = bq[j];
        else if (j < 512)  v = bk[j - 256];
        else if (j < 768)  v = bv[j - 512];
        else if (j < 1024) v = bskip[j - 768];
        else {
            int h = (j - 1024) >> 8, d = (j - 1024) & 255;
            float s = 0.f;
            for (int c = 0; c < 128; c++)
                s = fmaf(bq[h * 128 + c], We[d * 256 + h * 128 + c], s);
            v = s;
        }
        g_bbig[j] = v;
    }
}

// ---------------------------------------------------------------------------
// A fragment conversion (mma.m16n8k16 A-layout, fp16), row stride lda
// ---------------------------------------------------------------------------
__global__ void conv_afrag_kernel(const float* __restrict__ A, int lda,
                                  unsigned int* __restrict__ dst,
                                  int M, int K) {
    int nKT = K >> 4;
    int total = MBK * nKT * 1024;
    int gid = blockIdx.x * blockDim.x + threadIdx.x;
    if (gid >= total) return;
    int u = gid & 1023;
    int mbkt = gid >> 10;
    int mb = mbkt / nKT, kt = mbkt - mb * nKT;
    int mt = u >> 7;
    int lane = (u >> 2) & 31;
    int reg = u & 3;
    int row = mb * 128 + mt * 16 + (lane >> 2) + ((reg & 1) ? 8 : 0);
    int kc  = kt * 16 + ((lane & 3) * 2) + ((reg & 2) ? 8 : 0);
    float v0 = 0.f, v1 = 0.f;
    if (row < M) {
        v0 = A[(size_t)row * lda + kc];
        v1 = A[(size_t)row * lda + kc + 1];
    }
    dst[gid] = packh2(v0, v1);
}

// ---------------------------------------------------------------------------
// B fragment conversion (mma.m16n8k16 B-layout, fp16)
// ---------------------------------------------------------------------------
__global__ void conv_bfrag_kernel(const float* __restrict__ B, int ldb,
                                  unsigned int* __restrict__ dst,
                                  int K, int nNB) {
    int nKT = K >> 4;
    int total = nNB * nKT * 1024;
    int gid = blockIdx.x * blockDim.x + threadIdx.x;
    if (gid >= total) return;
    int reg = gid & 1;
    int lane = (gid >> 1) & 31;
    int nt = (gid >> 6) & 15;
    int nbkt = gid >> 10;
    int nb = nbkt / nKT, kt = nbkt - nb * nKT;
    int n = nb * 128 + nt * 8 + (lane >> 2);
    int k = kt * 16 + (lane & 3) * 2 + (reg ? 8 : 0);
    dst[gid] = packh2(B[(size_t)k * ldb + n], B[(size_t)(k + 1) * ldb + n]);
}

// ---------------------------------------------------------------------------
// Tensor-core GEMM via mma.sync fp16 (fragment-direct, no smem).
// 256 threads = 8 warps (2 wy x 4 wx), warp tile 64 x 32.
// SKIP768: columns [768,1024) are redirected to Cskip (ldc 256, col-768).
// ---------------------------------------------------------------------------
#define MMA_F16(c, a, b)                                                        \
    asm volatile("mma.sync.aligned.m16n8k16.row.col.f32.f16.f16.f32 "           \
        "{%0,%1,%2,%3}, {%4,%5,%6,%7}, {%8,%9}, {%0,%1,%2,%3};"                 \
        : "+f"((c)[0]), "+f"((c)[1]), "+f"((c)[2]), "+f"((c)[3])                \
        : "r"((a).x), "r"((a).y), "r"((a).z), "r"((a).w), "r"((b).x), "r"((b).y))

template <bool ACCUM, bool HASBIAS, bool SKIP768>
__global__ void __launch_bounds__(256)
mma_gemm(const uint4* __restrict__ Af, const uint2* __restrict__ Bf,
         float* __restrict__ C, float* __restrict__ Cskip,
         const float* __restrict__ bias,
         int M, int ldc, int nKT) {
    const int mb = blockIdx.x, nb = blockIdx.y;
    const int tid = threadIdx.x, lane = tid & 31, wid = tid >> 5;
    const int wy = wid >> 2, wx = wid & 3;

    float acc[4][4][4];
#pragma unroll
    for (int i = 0; i < 4; i++)
#pragma unroll
        for (int j = 0; j < 4; j++)
#pragma unroll
            for (int r = 0; r < 4; r++) acc[i][j][r] = 0.f;

    for (int kt = 0; kt < nKT; kt++) {
        uint4 a[4];
#pragma unroll
        for (int i = 0; i < 4; i++)
            a[i] = Af[((size_t)(mb * nKT + kt) * 8 + wy * 4 + i) * 32 + lane];
        uint2 b[4];
#pragma unroll
        for (int j = 0; j < 4; j++)
            b[j] = Bf[((size_t)(nb * nKT + kt) * 16 + wx * 4 + j) * 32 + lane];
#pragma unroll
        for (int i = 0; i < 4; i++)
#pragma unroll
            for (int j = 0; j < 4; j++)
                MMA_F16(acc[i][j], a[i], b[j]);
    }

#pragma unroll
    for (int i = 0; i < 4; i++) {
#pragma unroll
        for (int j = 0; j < 4; j++) {
            int row0 = mb * 128 + wy * 64 + i * 16 + (lane >> 2);
            int col  = nb * 128 + wx * 32 + j * 8 + (lane & 3) * 2;
            float b0 = 0.f, b1 = 0.f;
            if (HASBIAS) { b0 = bias[col]; b1 = bias[col + 1]; }
            bool toskip = SKIP768 && (col >= 768) && (col < 1024);
#pragma unroll
            for (int half = 0; half < 2; half++) {
                int row = row0 + half * 8;
                if (row >= M) continue;
                float* p = toskip ? &Cskip[(size_t)row * 256 + (col - 768)]
                                  : &C[(size_t)row * ldc + col];
                float2 v = make_float2(acc[i][j][2 * half + 0] + b0,
                                       acc[i][j][2 * half + 1] + b1);
                if (ACCUM) { float2 o = *reinterpret_cast<float2*>(p); v.x += o.x; v.y += o.y; }
                *reinterpret_cast<float2*>(p) = v;
            }
        }
    }
}

// ---------------------------------------------------------------------------
// Fused warp-per-node attention with index prefetch (no atomics).
// ---------------------------------------------------------------------------
__global__ void node_fused_kernel(const int* __restrict__ ei,
                                  const float* __restrict__ last_update,
                                  const float* __restrict__ t,
                                  const float* __restrict__ msg,
                                  const float* __restrict__ Wt,
                                  const float* __restrict__ bt,
                                  float* __restrict__ out,
                                  int E, int N) {
    int n = (blockIdx.x * blockDim.x + threadIdx.x) >> 5;
    if (n >= N) return;
    int lane = threadIdx.x & 31;

    const float* nf = &g_nf[(size_t)n * 1536];
    float q[8], qw0[8], qw1[8];
#pragma unroll
    for (int i = 0; i < 8; i++) {
        q[i]   = nf[lane + 32 * i];
        qw0[i] = nf[1024 + lane + 32 * i];
        qw1[i] = nf[1280 + lane + 32 * i];
    }
    float wtr[4], btr[4];
#pragma unroll
    for (int i = 0; i < 4; i++) { wtr[i] = Wt[lane + 32 * i]; btr[i] = bt[lane + 32 * i]; }

    float agg0[8], agg1[8], vac[8];
#pragma unroll
    for (int i = 0; i < 8; i++) { agg0[i] = 0.f; agg1[i] = 0.f; vac[i] = 0.f; }
    float asum0 = 0.f, asum1 = 0.f;

    int beg = g_rowptr[n], end = g_rowptr[n + 1];

    int e_n = 0, src_n = 0;
    float rel_n = 0.f;
    if (beg < end) {
        e_n = g_esorted[beg];
        src_n = clampi(ei[e_n], N);
        rel_n = last_update[src_n] - t[e_n];
    }

    for (int i = beg; i < end; i++) {
        int e = e_n, src = src_n;
        float rel_t = rel_n;
        if (i + 1 < end) {
            e_n = g_esorted[i + 1];
            src_n = clampi(ei[e_n], N);
            rel_n = last_update[src_n] - t[e_n];
        }

        const float* krow = &g_nf[(size_t)src * 1536 + 256];
        const float* vrow = &g_nf[(size_t)src * 1536 + 512];
        const float* mrow = &msg[(size_t)e * 128];

        float ea[8], vv[8];
        float s0 = 0.f, s1 = 0.f;
#pragma unroll
        for (int ii = 0; ii < 4; ii++) {
            int d = lane + 32 * ii;
            ea[ii] = cos_small(fmaf(rel_t, wtr[ii], btr[ii]));
            vv[ii] = vrow[d];
            s0 = fmaf(q[ii], krow[d], s0);
            s0 = fmaf(qw0[ii], ea[ii], s0);
            s1 = fmaf(qw1[ii], ea[ii], s1);
        }
#pragma unroll
        for (int ii = 4; ii < 8; ii++) {
            int d = lane + 32 * ii;
            ea[ii] = mrow[d - 128];
            vv[ii] = vrow[d];
            s1 = fmaf(q[ii], krow[d], s1);
            s0 = fmaf(qw0[ii], ea[ii], s0);
            s1 = fmaf(qw1[ii], ea[ii], s1);
        }
#pragma unroll
        for (int off = 16; off; off >>= 1) {
            s0 += __shfl_xor_sync(0xffffffffu, s0, off);
            s1 += __shfl_xor_sync(0xffffffffu, s1, off);
        }
        float a0 = __expf(s0 * RSQRT_C);
        float a1 = __expf(s1 * RSQRT_C);
        asum0 += a0;
        asum1 += a1;
#pragma unroll
        for (int ii = 0; ii < 8; ii++) {
            agg0[ii] = fmaf(a0, ea[ii], agg0[ii]);
            agg1[ii] = fmaf(a1, ea[ii], agg1[ii]);
        }
#pragma unroll
        for (int ii = 0; ii < 4; ii++) vac[ii] = fmaf(a0, vv[ii], vac[ii]);
#pragma unroll
        for (int ii = 4; ii < 8; ii++) vac[ii] = fmaf(a1, vv[ii], vac[ii]);
    }

    float inv0 = 1.f / (asum0 + 1e-16f);
    float inv1 = 1.f / (asum1 + 1e-16f);

    float* aggrow = &g_agg[(size_t)n * 512];
#pragma unroll
    for (int ii = 0; ii < 8; ii++) {
        aggrow[lane + 32 * ii]       = agg0[ii] * inv0;
        aggrow[256 + lane + 32 * ii] = agg1[ii] * inv1;
    }
    float* orow = &out[(size_t)n * 256];
#pragma unroll
    for (int ii = 0; ii < 4; ii++) {
        int idx = lane + 32 * ii;
        orow[idx]       += vac[ii] * inv0;
        orow[idx + 128] += vac[ii + 4] * inv1;
    }
}

// ---------------------------------------------------------------------------
// Host launcher
// ---------------------------------------------------------------------------
extern "C" void kernel_launch(void* const* d_in, const int* in_sizes, int n_in,
                              void* d_out, int out_size) {
    const float* x     = (const float*)d_in[0];
    const float* lastu = (const float*)d_in[1];
    const float* t     = (const float*)d_in[2];
    const float* msg   = (const float*)d_in[3];
    const int*   ei    = (const int*)d_in[4];   // int32 (JAX x64 disabled)
    const float* Wt    = (const float*)d_in[5];
    const float* bt    = (const float*)d_in[6];
    const float* Wq    = (const float*)d_in[7];
    const float* bq    = (const float*)d_in[8];
    const float* Wk    = (const float*)d_in[9];
    const float* bk    = (const float*)d_in[10];
    const float* Wv    = (const float*)d_in[11];
    const float* bv    = (const float*)d_in[12];
    const float* We    = (const float*)d_in[13];
    const float* Wskip = (const float*)d_in[14];
    const float* bskip = (const float*)d_in[15];
    float* out = (float*)d_out;

    const int N = in_sizes[0] / INCH;   // 50000
    const int E = in_sizes[2];          // 400000

    float *pNF, *pAGG, *pWBIG, *pBBIG;
    int *pDEG;
    unsigned int *pA1, *pAG, *pB1, *pB2;
    cudaGetSymbolAddress((void**)&pNF,   g_nf);
    cudaGetSymbolAddress((void**)&pAGG,  g_agg);
    cudaGetSymbolAddress((void**)&pWBIG, g_wbig);
    cudaGetSymbolAddress((void**)&pBBIG, g_bbig);
    cudaGetSymbolAddress((void**)&pDEG,  g_deg);
    cudaGetSymbolAddress((void**)&pA1,   g_a1);
    cudaGetSymbolAddress((void**)&pAG,   g_ag);
    cudaGetSymbolAddress((void**)&pB1,   g_b1);
    cudaGetSymbolAddress((void**)&pB2,   g_b2);

    // 0) CSR build
    zero_int_kernel<<<(N + 255) / 256, 256>>>(pDEG, N);
    hist_kernel<<<(E + 255) / 256, 256>>>(ei, E, N);
    scan_kernel<<<1, 1024>>>(N);
    scatter_kernel<<<(E + 255) / 256, 256>>>(ei, E, N);

    // 1) weight prep -> fragment conversion
    pack_wbig_kernel<<<(256 * 1536 + 255) / 256, 256>>>(Wq, bq, Wk, bk, Wv, bv, Wskip, bskip, We);
    conv_bfrag_kernel<<<(12 * 16 * 1024 + 255) / 256, 256>>>(pWBIG, 1536, pB1, 256, 12);
    for (int h = 0; h < 2; h++)
        conv_bfrag_kernel<<<(16 * 1024 + 255) / 256, 256>>>(
            We + h * 128, 256, pB2 + h * 16 * 1024, 256, 1);

    // 2) x -> A fragments; GEMM1: g_nf = x @ Wbig + bbig (skip cols -> out)
    conv_afrag_kernel<<<(MBK * 16 * 1024 + 255) / 256, 256>>>(x, 256, pA1, N, 256);
    mma_gemm<false, true, true><<<dim3(MBK, 12), 256>>>(
        (const uint4*)pA1, (const uint2*)pB1, pNF, out, pBBIG, N, 1536, 16);

    // 3) fused attention pass (writes g_agg, accumulates v-part into out)
    node_fused_kernel<<<(N * 32 + 255) / 256, 256>>>(ei, lastu, t, msg, Wt, bt, out, E, N);

    // 4) per-head agg -> A fragments; GEMM2: out[:, h*128:] += agg_h @ We_h
    for (int h = 0; h < 2; h++) {
        conv_afrag_kernel<<<(MBK * 16 * 1024 + 255) / 256, 256>>>(
            pAGG + h * 256, 512, pAG + (size_t)h * MBK * 16 * 1024, N, 256);
        mma_gemm<true, false, false><<<dim3(MBK, 1), 256>>>(
            (const uint4*)(pAG + (size_t)h * MBK * 16 * 1024),
            (const uint2*)(pB2 + h * 16 * 1024),
            out + h * 128, nullptr, nullptr, N, 256, 16);
    }
}

// round 16
// speedup vs baseline: 1.6921x; 1.1252x over previous
#include <cuda_runtime.h>
#include <cuda_fp16.h>
#include <cstdint>

// ---------------------------------------------------------------------------
// Problem constants
// ---------------------------------------------------------------------------
#define NMAX 50000
#define EMAX 400000
#define INCH 256
#define MBK   391                     // ceil(50000/128)
#define RSQRT_C 0.08838834764831845f  // 1/sqrt(128)

// ---------------------------------------------------------------------------
// Scratch (static __device__; allocation APIs are forbidden)
// ---------------------------------------------------------------------------
__device__ float g_nf[(size_t)NMAX * 1536];     // [q|..|..|(skip->out)|qw0|qw1]
__device__ unsigned int g_kv[(size_t)NMAX * 256];    // fp16 pairs: [k 128 | v 128]
__device__ unsigned int g_agg16[(size_t)NMAX * 256]; // fp16 pairs of 512-col agg
__device__ float g_wbig[256 * 1536];            // fp32 combined weight [k][n]
__device__ float g_bbig[1536];
__device__ int   g_deg[NMAX];
__device__ int   g_rowptr[NMAX + 1];
__device__ int   g_cursor[NMAX];
__device__ int   g_esorted[EMAX];

// Fragment-ordered fp16 operands (uint = packed half2).
__align__(16) __device__ unsigned int g_a1[(size_t)MBK * 16 * 1024];
__align__(16) __device__ unsigned int g_ag[(size_t)MBK * 32 * 1024];   // 2 heads
__align__(16) __device__ unsigned int g_b1[12 * 16 * 1024];
__align__(16) __device__ unsigned int g_b2[2 * 16 * 1024];

// ---------------------------------------------------------------------------
// Helpers
// ---------------------------------------------------------------------------
__device__ __forceinline__ float cos_small(float u) {
    float s = u * u;
    float p = fmaf(s, 2.48015873e-5f, -1.38888889e-3f);
    p = fmaf(p, s, 4.16666667e-2f);
    p = fmaf(p, s, -0.5f);
    return fmaf(p, s, 1.0f);
}
__device__ __forceinline__ int clampi(int v, int hi) {
    return v < 0 ? 0 : (v >= hi ? hi - 1 : v);
}
__device__ __forceinline__ unsigned int packh2(float v0, float v1) {
    __half2 h = __floats2half2_rn(v0, v1);
    return *reinterpret_cast<unsigned int*>(&h);
}
__device__ __forceinline__ float2 unpackh2(unsigned int u) {
    __half2 h = *reinterpret_cast<__half2*>(&u);
    return __half22float2(h);
}

__global__ void zero_int_kernel(int* __restrict__ p, int n) {
    int i = blockIdx.x * blockDim.x + threadIdx.x;
    if (i < n) p[i] = 0;
}

// ---------------------------------------------------------------------------
// CSR build: histogram -> single-block scan -> scatter
// ---------------------------------------------------------------------------
__global__ void hist_kernel(const int* __restrict__ ei, int E, int N) {
    int e = blockIdx.x * blockDim.x + threadIdx.x;
    if (e >= E) return;
    atomicAdd(&g_deg[clampi(ei[E + e], N)], 1);
}

__global__ void scan_kernel(int N) {
    __shared__ int part[1024];
    int tid = threadIdx.x;
    int chunk = (N + 1023) >> 10;
    int start = tid * chunk;
    int end = min(start + chunk, N);
    int s = 0;
    for (int i = start; i < end; i++) s += g_deg[i];
    part[tid] = s;
    __syncthreads();
    for (int off = 1; off < 1024; off <<= 1) {
        int v = (tid >= off) ? part[tid - off] : 0;
        __syncthreads();
        part[tid] += v;
        __syncthreads();
    }
    int base = (tid == 0) ? 0 : part[tid - 1];
    for (int i = start; i < end; i++) {
        g_rowptr[i] = base;
        g_cursor[i] = base;
        base += g_deg[i];
    }
    if (tid == 1023) g_rowptr[N] = part[1023];
}

__global__ void scatter_kernel(const int* __restrict__ ei, int E, int N) {
    int e = blockIdx.x * blockDim.x + threadIdx.x;
    if (e >= E) return;
    int dst = clampi(ei[E + e], N);
    int pos = atomicAdd(&g_cursor[dst], 1);
    g_esorted[pos] = e;
}

// ---------------------------------------------------------------------------
// Weight prep: Wbig[256 x 1536] = [Wq|Wk|Wv|Wskip|Wqe0|Wqe1], bias similarly.
// ---------------------------------------------------------------------------
__global__ void pack_wbig_kernel(const float* __restrict__ Wq, const float* __restrict__ bq,
                                 const float* __restrict__ Wk, const float* __restrict__ bk,
                                 const float* __restrict__ Wv, const float* __restrict__ bv,
                                 const float* __restrict__ Wskip, const float* __restrict__ bskip,
                                 const float* __restrict__ We) {
    int gid = blockIdx.x * blockDim.x + threadIdx.x;
    if (gid < 256 * 1536) {
        int i = gid / 1536, j = gid % 1536;
        float v;
        if      (j < 256)  v = Wq[i * 256 + j];
        else if (j < 512)  v = Wk[i * 256 + (j - 256)];
        else if (j < 768)  v = Wv[i * 256 + (j - 512)];
        else if (j < 1024) v = Wskip[i * 256 + (j - 768)];
        else {
            int h = (j - 1024) >> 8, d = (j - 1024) & 255;
            float s = 0.f;
            for (int c = 0; c < 128; c++)
                s = fmaf(Wq[i * 256 + h * 128 + c], We[d * 256 + h * 128 + c], s);
            v = s;
        }
        g_wbig[gid] = v;
    }
    if (gid < 1536) {
        int j = gid;
        float v;
        if      (j < 256)  v = bq[j];
        else if (j < 512)  v = bk[j - 256];
        else if (j < 768)  v = bv[j - 512];
        else if (j < 1024) v = bskip[j - 768];
        else {
            int h = (j - 1024) >> 8, d = (j - 1024) & 255;
            float s = 0.f;
            for (int c = 0; c < 128; c++)
                s = fmaf(bq[h * 128 + c], We[d * 256 + h * 128 + c], s);
            v = s;
        }
        g_bbig[j] = v;
    }
}

// ---------------------------------------------------------------------------
// A fragment conversion (mma.m16n8k16 A-layout, fp16 from fp32), stride lda
// ---------------------------------------------------------------------------
__global__ void conv_afrag_kernel(const float* __restrict__ A, int lda,
                                  unsigned int* __restrict__ dst,
                                  int M, int K) {
    int nKT = K >> 4;
    int total = MBK * nKT * 1024;
    int gid = blockIdx.x * blockDim.x + threadIdx.x;
    if (gid >= total) return;
    int u = gid & 1023;
    int mbkt = gid >> 10;
    int mb = mbkt / nKT, kt = mbkt - mb * nKT;
    int mt = u >> 7;
    int lane = (u >> 2) & 31;
    int reg = u & 3;
    int row = mb * 128 + mt * 16 + (lane >> 2) + ((reg & 1) ? 8 : 0);
    int kc  = kt * 16 + ((lane & 3) * 2) + ((reg & 2) ? 8 : 0);
    float v0 = 0.f, v1 = 0.f;
    if (row < M) {
        v0 = A[(size_t)row * lda + kc];
        v1 = A[(size_t)row * lda + kc + 1];
    }
    dst[gid] = packh2(v0, v1);
}

// ---------------------------------------------------------------------------
// A fragment relayout from fp16 pair buffer (g_agg16): pure uint copy.
// head selects agg columns [head*256, head*256+256); K=256, nKT=16.
// ---------------------------------------------------------------------------
__global__ void conv_afrag_h_kernel(const unsigned int* __restrict__ src, int head,
                                    unsigned int* __restrict__ dst, int M) {
    int total = MBK * 16 * 1024;
    int gid = blockIdx.x * blockDim.x + threadIdx.x;
    if (gid >= total) return;
    int u = gid & 1023;
    int mbkt = gid >> 10;
    int mb = mbkt >> 4, kt = mbkt & 15;
    int mt = u >> 7;
    int lane = (u >> 2) & 31;
    int reg = u & 3;
    int row = mb * 128 + mt * 16 + (lane >> 2) + ((reg & 1) ? 8 : 0);
    int kc  = kt * 16 + ((lane & 3) * 2) + ((reg & 2) ? 8 : 0);
    dst[gid] = (row < M) ? src[(size_t)row * 256 + head * 128 + (kc >> 1)] : 0u;
}

// ---------------------------------------------------------------------------
// B fragment conversion (mma.m16n8k16 B-layout, fp16)
// ---------------------------------------------------------------------------
__global__ void conv_bfrag_kernel(const float* __restrict__ B, int ldb,
                                  unsigned int* __restrict__ dst,
                                  int K, int nNB) {
    int nKT = K >> 4;
    int total = nNB * nKT * 1024;
    int gid = blockIdx.x * blockDim.x + threadIdx.x;
    if (gid >= total) return;
    int reg = gid & 1;
    int lane = (gid >> 1) & 31;
    int nt = (gid >> 6) & 15;
    int nbkt = gid >> 10;
    int nb = nbkt / nKT, kt = nbkt - nb * nKT;
    int n = nb * 128 + nt * 8 + (lane >> 2);
    int k = kt * 16 + (lane & 3) * 2 + (reg ? 8 : 0);
    dst[gid] = packh2(B[(size_t)k * ldb + n], B[(size_t)(k + 1) * ldb + n]);
}

// ---------------------------------------------------------------------------
// Tensor-core GEMM via mma.sync fp16 (fragment-direct, no smem).
// 256 threads = 8 warps (2 wy x 4 wx), warp tile 64 x 32.
// SKIP768 (GEMM1 only): cols [256,768) -> g_kv (fp16 pairs);
//                       cols [768,1024) -> Cskip (ldc 256, col-768).
// ---------------------------------------------------------------------------
#define MMA_F16(c, a, b)                                                        \
    asm volatile("mma.sync.aligned.m16n8k16.row.col.f32.f16.f16.f32 "           \
        "{%0,%1,%2,%3}, {%4,%5,%6,%7}, {%8,%9}, {%0,%1,%2,%3};"                 \
        : "+f"((c)[0]), "+f"((c)[1]), "+f"((c)[2]), "+f"((c)[3])                \
        : "r"((a).x), "r"((a).y), "r"((a).z), "r"((a).w), "r"((b).x), "r"((b).y))

template <bool ACCUM, bool HASBIAS, bool SKIP768>
__global__ void __launch_bounds__(256)
mma_gemm(const uint4* __restrict__ Af, const uint2* __restrict__ Bf,
         float* __restrict__ C, float* __restrict__ Cskip,
         const float* __restrict__ bias,
         int M, int ldc, int nKT) {
    const int mb = blockIdx.x, nb = blockIdx.y;
    const int tid = threadIdx.x, lane = tid & 31, wid = tid >> 5;
    const int wy = wid >> 2, wx = wid & 3;

    float acc[4][4][4];
#pragma unroll
    for (int i = 0; i < 4; i++)
#pragma unroll
        for (int j = 0; j < 4; j++)
#pragma unroll
            for (int r = 0; r < 4; r++) acc[i][j][r] = 0.f;

    for (int kt = 0; kt < nKT; kt++) {
        uint4 a[4];
#pragma unroll
        for (int i = 0; i < 4; i++)
            a[i] = Af[((size_t)(mb * nKT + kt) * 8 + wy * 4 + i) * 32 + lane];
        uint2 b[4];
#pragma unroll
        for (int j = 0; j < 4; j++)
            b[j] = Bf[((size_t)(nb * nKT + kt) * 16 + wx * 4 + j) * 32 + lane];
#pragma unroll
        for (int i = 0; i < 4; i++)
#pragma unroll
            for (int j = 0; j < 4; j++)
                MMA_F16(acc[i][j], a[i], b[j]);
    }

#pragma unroll
    for (int i = 0; i < 4; i++) {
#pragma unroll
        for (int j = 0; j < 4; j++) {
            int row0 = mb * 128 + wy * 64 + i * 16 + (lane >> 2);
            int col  = nb * 128 + wx * 32 + j * 8 + (lane & 3) * 2;
            float b0 = 0.f, b1 = 0.f;
            if (HASBIAS) { b0 = bias[col]; b1 = bias[col + 1]; }
#pragma unroll
            for (int half = 0; half < 2; half++) {
                int row = row0 + half * 8;
                if (row >= M) continue;
                float x0 = acc[i][j][2 * half + 0] + b0;
                float x1 = acc[i][j][2 * half + 1] + b1;
                if (SKIP768 && col >= 256 && col < 768) {
                    g_kv[(size_t)row * 256 + ((col - 256) >> 1)] = packh2(x0, x1);
                } else {
                    float* p = (SKIP768 && col >= 768 && col < 1024)
                             ? &Cskip[(size_t)row * 256 + (col - 768)]
                             : &C[(size_t)row * ldc + col];
                    float2 v = make_float2(x0, x1);
                    if (ACCUM) { float2 o = *reinterpret_cast<float2*>(p); v.x += o.x; v.y += o.y; }
                    *reinterpret_cast<float2*>(p) = v;
                }
            }
        }
    }
}

// ---------------------------------------------------------------------------
// Fused warp-per-node attention, pair-mapped lanes (lane owns column pairs
// 64*ii + 2*lane). k/v gathered as fp16 pairs from g_kv; agg written fp16.
// No atomics.
// ---------------------------------------------------------------------------
__global__ void node_fused_kernel(const int* __restrict__ ei,
                                  const float* __restrict__ last_update,
                                  const float* __restrict__ t,
                                  const float* __restrict__ msg,
                                  const float* __restrict__ Wt,
                                  const float* __restrict__ bt,
                                  float* __restrict__ out,
                                  int E, int N) {
    int n = (blockIdx.x * blockDim.x + threadIdx.x) >> 5;
    if (n >= N) return;
    int lane = threadIdx.x & 31;

    const float* nf = &g_nf[(size_t)n * 1536];
    float2 q2[4], qa2[4], qb2[4];
#pragma unroll
    for (int i = 0; i < 4; i++) {
        q2[i]  = *reinterpret_cast<const float2*>(&nf[64 * i + 2 * lane]);
        qa2[i] = *reinterpret_cast<const float2*>(&nf[1024 + 64 * i + 2 * lane]);
        qb2[i] = *reinterpret_cast<const float2*>(&nf[1280 + 64 * i + 2 * lane]);
    }
    float2 wt2[2], bt2[2];
#pragma unroll
    for (int i = 0; i < 2; i++) {
        wt2[i] = *reinterpret_cast<const float2*>(&Wt[64 * i + 2 * lane]);
        bt2[i] = *reinterpret_cast<const float2*>(&bt[64 * i + 2 * lane]);
    }

    float2 agg0[4], agg1[4], vac[4];
#pragma unroll
    for (int i = 0; i < 4; i++) {
        agg0[i] = make_float2(0.f, 0.f);
        agg1[i] = make_float2(0.f, 0.f);
        vac[i]  = make_float2(0.f, 0.f);
    }
    float asum0 = 0.f, asum1 = 0.f;

    int beg = g_rowptr[n], end = g_rowptr[n + 1];

    int e_n = 0, src_n = 0;
    float rel_n = 0.f;
    if (beg < end) {
        e_n = g_esorted[beg];
        src_n = clampi(ei[e_n], N);
        rel_n = last_update[src_n] - t[e_n];
    }

    for (int i = beg; i < end; i++) {
        int e = e_n, src = src_n;
        float rel_t = rel_n;
        if (i + 1 < end) {
            e_n = g_esorted[i + 1];
            src_n = clampi(ei[e_n], N);
            rel_n = last_update[src_n] - t[e_n];
        }

        const unsigned int* kvrow = &g_kv[(size_t)src * 256];
        unsigned int ku[4], vu[4];
#pragma unroll
        for (int ii = 0; ii < 4; ii++) {
            ku[ii] = kvrow[32 * ii + lane];
            vu[ii] = kvrow[128 + 32 * ii + lane];
        }
        float2 ea[4];
        ea[0] = make_float2(cos_small(fmaf(rel_t, wt2[0].x, bt2[0].x)),
                            cos_small(fmaf(rel_t, wt2[0].y, bt2[0].y)));
        ea[1] = make_float2(cos_small(fmaf(rel_t, wt2[1].x, bt2[1].x)),
                            cos_small(fmaf(rel_t, wt2[1].y, bt2[1].y)));
        ea[2] = *reinterpret_cast<const float2*>(&msg[(size_t)e * 128 + 2 * lane]);
        ea[3] = *reinterpret_cast<const float2*>(&msg[(size_t)e * 128 + 64 + 2 * lane]);

        float s0 = 0.f, s1 = 0.f;
#pragma unroll
        for (int ii = 0; ii < 4; ii++) {
            float2 k2 = unpackh2(ku[ii]);
            if (ii < 2) { s0 = fmaf(q2[ii].x, k2.x, s0); s0 = fmaf(q2[ii].y, k2.y, s0); }
            else        { s1 = fmaf(q2[ii].x, k2.x, s1); s1 = fmaf(q2[ii].y, k2.y, s1); }
            s0 = fmaf(qa2[ii].x, ea[ii].x, s0); s0 = fmaf(qa2[ii].y, ea[ii].y, s0);
            s1 = fmaf(qb2[ii].x, ea[ii].x, s1); s1 = fmaf(qb2[ii].y, ea[ii].y, s1);
        }
#pragma unroll
        for (int off = 16; off; off >>= 1) {
            s0 += __shfl_xor_sync(0xffffffffu, s0, off);
            s1 += __shfl_xor_sync(0xffffffffu, s1, off);
        }
        float a0 = __expf(s0 * RSQRT_C);
        float a1 = __expf(s1 * RSQRT_C);
        asum0 += a0;
        asum1 += a1;
#pragma unroll
        for (int ii = 0; ii < 4; ii++) {
            agg0[ii].x = fmaf(a0, ea[ii].x, agg0[ii].x);
            agg0[ii].y = fmaf(a0, ea[ii].y, agg0[ii].y);
            agg1[ii].x = fmaf(a1, ea[ii].x, agg1[ii].x);
            agg1[ii].y = fmaf(a1, ea[ii].y, agg1[ii].y);
            float2 v2 = unpackh2(vu[ii]);
            float ah = (ii < 2) ? a0 : a1;
            vac[ii].x = fmaf(ah, v2.x, vac[ii].x);
            vac[ii].y = fmaf(ah, v2.y, vac[ii].y);
        }
    }

    float inv0 = 1.f / (asum0 + 1e-16f);
    float inv1 = 1.f / (asum1 + 1e-16f);

    unsigned int* arow = &g_agg16[(size_t)n * 256];
#pragma unroll
    for (int ii = 0; ii < 4; ii++) {
        arow[32 * ii + lane]       = packh2(agg0[ii].x * inv0, agg0[ii].y * inv0);
        arow[128 + 32 * ii + lane] = packh2(agg1[ii].x * inv1, agg1[ii].y * inv1);
    }
    float* orow = &out[(size_t)n * 256];
#pragma unroll
    for (int ii = 0; ii < 4; ii++) {
        float inv = (ii < 2) ? inv0 : inv1;
        float2* p = reinterpret_cast<float2*>(&orow[64 * ii + 2 * lane]);
        float2 o = *p;
        o.x = fmaf(vac[ii].x, inv, o.x);
        o.y = fmaf(vac[ii].y, inv, o.y);
        *p = o;
    }
}

// ---------------------------------------------------------------------------
// Host launcher
// ---------------------------------------------------------------------------
extern "C" void kernel_launch(void* const* d_in, const int* in_sizes, int n_in,
                              void* d_out, int out_size) {
    const float* x     = (const float*)d_in[0];
    const float* lastu = (const float*)d_in[1];
    const float* t     = (const float*)d_in[2];
    const float* msg   = (const float*)d_in[3];
    const int*   ei    = (const int*)d_in[4];   // int32 (JAX x64 disabled)
    const float* Wt    = (const float*)d_in[5];
    const float* bt    = (const float*)d_in[6];
    const float* Wq    = (const float*)d_in[7];
    const float* bq    = (const float*)d_in[8];
    const float* Wk    = (const float*)d_in[9];
    const float* bk    = (const float*)d_in[10];
    const float* Wv    = (const float*)d_in[11];
    const float* bv    = (const float*)d_in[12];
    const float* We    = (const float*)d_in[13];
    const float* Wskip = (const float*)d_in[14];
    const float* bskip = (const float*)d_in[15];
    float* out = (float*)d_out;

    const int N = in_sizes[0] / INCH;   // 50000
    const int E = in_sizes[2];          // 400000

    float *pNF, *pWBIG, *pBBIG;
    int *pDEG;
    unsigned int *pA1, *pAG, *pB1, *pB2, *pAGG16;
    cudaGetSymbolAddress((void**)&pNF,    g_nf);
    cudaGetSymbolAddress((void**)&pWBIG,  g_wbig);
    cudaGetSymbolAddress((void**)&pBBIG,  g_bbig);
    cudaGetSymbolAddress((void**)&pDEG,   g_deg);
    cudaGetSymbolAddress((void**)&pA1,    g_a1);
    cudaGetSymbolAddress((void**)&pAG,    g_ag);
    cudaGetSymbolAddress((void**)&pB1,    g_b1);
    cudaGetSymbolAddress((void**)&pB2,    g_b2);
    cudaGetSymbolAddress((void**)&pAGG16, g_agg16);

    // 0) CSR build
    zero_int_kernel<<<(N + 255) / 256, 256>>>(pDEG, N);
    hist_kernel<<<(E + 255) / 256, 256>>>(ei, E, N);
    scan_kernel<<<1, 1024>>>(N);
    scatter_kernel<<<(E + 255) / 256, 256>>>(ei, E, N);

    // 1) weight prep -> fragment conversion
    pack_wbig_kernel<<<(256 * 1536 + 255) / 256, 256>>>(Wq, bq, Wk, bk, Wv, bv, Wskip, bskip, We);
    conv_bfrag_kernel<<<(12 * 16 * 1024 + 255) / 256, 256>>>(pWBIG, 1536, pB1, 256, 12);
    for (int h = 0; h < 2; h++)
        conv_bfrag_kernel<<<(16 * 1024 + 255) / 256, 256>>>(
            We + h * 128, 256, pB2 + h * 16 * 1024, 256, 1);

    // 2) x -> A fragments; GEMM1: q|qw -> g_nf, k|v -> g_kv fp16, skip -> out
    conv_afrag_kernel<<<(MBK * 16 * 1024 + 255) / 256, 256>>>(x, 256, pA1, N, 256);
    mma_gemm<false, true, true><<<dim3(MBK, 12), 256>>>(
        (const uint4*)pA1, (const uint2*)pB1, pNF, out, pBBIG, N, 1536, 16);

    // 3) fused attention pass (writes g_agg16 fp16, accumulates v-part into out)
    node_fused_kernel<<<(N * 32 + 255) / 256, 256>>>(ei, lastu, t, msg, Wt, bt, out, E, N);

    // 4) per-head agg16 -> A fragments (uint relayout); GEMM2: out += agg_h @ We_h
    for (int h = 0; h < 2; h++) {
        conv_afrag_h_kernel<<<(MBK * 16 * 1024 + 255) / 256, 256>>>(
            pAGG16, h, pAG + (size_t)h * MBK * 16 * 1024, N);
        mma_gemm<true, false, false><<<dim3(MBK, 1), 256>>>(
            (const uint4*)(pAG + (size_t)h * MBK * 16 * 1024),
            (const uint2*)(pB2 + h * 16 * 1024),
            out + h * 128, nullptr, nullptr, N, 256, 16);
    }
}